// round 1
// baseline (speedup 1.0000x reference)
#include <cuda_runtime.h>
#include <math.h>

#define B_   4
#define S_   2048
#define HID_ 1024
#define NH_  4
#define D_   256
#define IM_  2048
#define E_   4
#define T_   (B_*S_)   // 8192 tokens

// ---------------- scratch (static device allocations; allowed) ----------------
__device__ float g_xn[(size_t)T_*HID_];
__device__ float g_q [(size_t)T_*HID_];
__device__ float g_k [(size_t)T_*HID_];
__device__ float g_v [(size_t)T_*HID_];
__device__ float g_scores[(size_t)B_*NH_*S_*S_];   // 256 MB
__device__ float g_o [(size_t)T_*HID_];
__device__ float g_h1[(size_t)T_*HID_];
__device__ float g_x2[(size_t)T_*HID_];
__device__ float g_rw[(size_t)T_*E_];
__device__ float g_gbuf[(size_t)T_*IM_];
__device__ float g_ubuf[(size_t)T_*IM_];
__device__ float g_red[S_];

// ---------------- block reductions ----------------
__device__ __forceinline__ float blk_sum(float v) {
    __shared__ float sm[32];
    __syncthreads();
    int lane = threadIdx.x & 31, w = threadIdx.x >> 5;
    #pragma unroll
    for (int o = 16; o; o >>= 1) v += __shfl_down_sync(0xffffffffu, v, o);
    if (lane == 0) sm[w] = v;
    __syncthreads();
    int nw = blockDim.x >> 5;
    if (w == 0) {
        v = (lane < nw) ? sm[lane] : 0.f;
        #pragma unroll
        for (int o = 16; o; o >>= 1) v += __shfl_down_sync(0xffffffffu, v, o);
        if (lane == 0) sm[0] = v;
    }
    __syncthreads();
    return sm[0];
}

__device__ __forceinline__ float blk_max(float v) {
    __shared__ float sm[32];
    __syncthreads();
    int lane = threadIdx.x & 31, w = threadIdx.x >> 5;
    #pragma unroll
    for (int o = 16; o; o >>= 1) v = fmaxf(v, __shfl_down_sync(0xffffffffu, v, o));
    if (lane == 0) sm[w] = v;
    __syncthreads();
    int nw = blockDim.x >> 5;
    if (w == 0) {
        v = (lane < nw) ? sm[lane] : -INFINITY;
        #pragma unroll
        for (int o = 16; o; o >>= 1) v = fmaxf(v, __shfl_down_sync(0xffffffffu, v, o));
        if (lane == 0) sm[0] = v;
    }
    __syncthreads();
    return sm[0];
}

// ---------------- rmsnorm: one block (256 thr) per token, HID=1024 ----------------
__global__ void rmsnorm_kernel(const float* __restrict__ x,
                               const float* __restrict__ w,
                               float* __restrict__ out) {
    size_t t = blockIdx.x;
    const float4* xp = (const float4*)(x + t * HID_);
    float4 v = xp[threadIdx.x];
    float s = v.x*v.x + v.y*v.y + v.z*v.z + v.w*v.w;
    s = blk_sum(s);
    float r = rsqrtf(s * (1.f / HID_) + 1e-6f);
    float4 wv = ((const float4*)w)[threadIdx.x];
    float4 o;
    o.x = v.x * wv.x * r; o.y = v.y * wv.y * r;
    o.z = v.z * wv.z * r; o.w = v.w * wv.w * r;
    ((float4*)(out + t * HID_))[threadIdx.x] = o;
}

// ---------------- generic tiled SGEMM ----------------
// C[M,N] = A[M,K] * B  (TB=false: B is [K,N] ldb;  TB=true: B is [N,K] ldb, i.e. A*B^T)
// Batched over blockIdx.z with (b,h) split strides (NH_=4).
// EPI: 0 store, 1 elu+1, 2 +aux(residual), 3 silu, 4 *aux (store), 5 aux + acc*rs[m], 6 C += acc*rs[m]
#define BM 128
#define BN 128
#define BK 16
#define TM 8
#define TN 8

template<int EPI, bool TB>
__global__ __launch_bounds__(256)
void gemm_kernel(int M, int N, int K,
                 const float* __restrict__ A, int lda, long sAb, long sAh,
                 const float* __restrict__ Bm, int ldb, long sBb, long sBh,
                 float* __restrict__ C, int ldc, long sCb, long sCh,
                 const float* __restrict__ aux,
                 const float* __restrict__ rs, int rsStride) {
    int z  = blockIdx.z;
    int zb = z >> 2, zh = z & 3;          // NH_ = 4
    A  += (long)zb * sAb + (long)zh * sAh;
    Bm += (long)zb * sBb + (long)zh * sBh;
    C  += (long)zb * sCb + (long)zh * sCh;

    __shared__ float As[BK][BM];
    __shared__ float Bs[BK][BN];

    int tid = threadIdx.x;
    int blockRow = blockIdx.y * BM;
    int blockCol = blockIdx.x * BN;
    int trow = (tid >> 4) * TM;           // 0..120
    int tcol = (tid & 15) * TN;           // 0..120

    int aRow = tid >> 2;                  // 0..63
    int aCol = (tid & 3) * 4;             // 0,4,8,12
    int bRow = tid >> 5;                  // 0..7
    int bCol = (tid & 31) * 4;            // 0..124

    float acc[TM][TN] = {};

    for (int k0 = 0; k0 < K; k0 += BK) {
        #pragma unroll
        for (int p = 0; p < 2; p++) {
            int r = aRow + p * 64;
            float4 v = *(const float4*)(A + (long)(blockRow + r) * lda + k0 + aCol);
            As[aCol + 0][r] = v.x; As[aCol + 1][r] = v.y;
            As[aCol + 2][r] = v.z; As[aCol + 3][r] = v.w;
        }
        if (!TB) {
            #pragma unroll
            for (int p = 0; p < 2; p++) {
                int r = bRow + p * 8;
                *(float4*)(&Bs[r][bCol]) =
                    *(const float4*)(Bm + (long)(k0 + r) * ldb + blockCol + bCol);
            }
        } else {
            #pragma unroll
            for (int p = 0; p < 2; p++) {
                int n = aRow + p * 64;
                float4 v = *(const float4*)(Bm + (long)(blockCol + n) * ldb + k0 + aCol);
                Bs[aCol + 0][n] = v.x; Bs[aCol + 1][n] = v.y;
                Bs[aCol + 2][n] = v.z; Bs[aCol + 3][n] = v.w;
            }
        }
        __syncthreads();

        #pragma unroll
        for (int kk = 0; kk < BK; kk++) {
            float ar[TM], br[TN];
            #pragma unroll
            for (int i = 0; i < TM; i++) ar[i] = As[kk][trow + i];
            #pragma unroll
            for (int j = 0; j < TN; j++) br[j] = Bs[kk][tcol + j];
            #pragma unroll
            for (int i = 0; i < TM; i++)
                #pragma unroll
                for (int j = 0; j < TN; j++)
                    acc[i][j] = fmaf(ar[i], br[j], acc[i][j]);
        }
        __syncthreads();
    }

    #pragma unroll
    for (int i = 0; i < TM; i++) {
        int m = blockRow + trow + i;
        float scale = 0.f;
        if (EPI == 5 || EPI == 6) scale = rs[(long)m * rsStride];
        #pragma unroll
        for (int j = 0; j < TN; j++) {
            int n = blockCol + tcol + j;
            long idx = (long)m * ldc + n;
            float v = acc[i][j];
            if      (EPI == 0) C[idx] = v;
            else if (EPI == 1) C[idx] = (v > 0.f) ? v + 1.f : expf(v);     // elu+1
            else if (EPI == 2) C[idx] = v + aux[idx];                      // + residual
            else if (EPI == 3) C[idx] = v / (1.f + expf(-v));              // silu
            else if (EPI == 4) C[idx] = v * aux[idx];                      // g*u
            else if (EPI == 5) C[idx] = aux[idx] + v * scale;              // h1 + d*rw
            else if (EPI == 6) C[idx] += v * scale;                        // += d*rw
        }
    }
}

// ---------------- softmax over rows of length S_=2048 ----------------
__global__ void softmax_kernel(float* __restrict__ x) {
    size_t row = blockIdx.x;
    float4* p = (float4*)(x + row * (size_t)S_);
    float4 a = p[threadIdx.x];
    float4 b = p[threadIdx.x + 256];
    float mx = fmaxf(fmaxf(fmaxf(a.x, a.y), fmaxf(a.z, a.w)),
                     fmaxf(fmaxf(b.x, b.y), fmaxf(b.z, b.w)));
    mx = blk_max(mx);
    a.x = expf(a.x - mx); a.y = expf(a.y - mx); a.z = expf(a.z - mx); a.w = expf(a.w - mx);
    b.x = expf(b.x - mx); b.y = expf(b.y - mx); b.z = expf(b.z - mx); b.w = expf(b.w - mx);
    float s = a.x + a.y + a.z + a.w + b.x + b.y + b.z + b.w;
    s = blk_sum(s);
    float inv = 1.f / s;
    a.x *= inv; a.y *= inv; a.z *= inv; a.w *= inv;
    b.x *= inv; b.y *= inv; b.z *= inv; b.w *= inv;
    p[threadIdx.x] = a;
    p[threadIdx.x + 256] = b;
}

// ---------------- router: logits = x2 @ W[HID,4] + b, softmax over 4 ----------------
__global__ void router_kernel(const float* __restrict__ x2,
                              const float* __restrict__ rwW,
                              const float* __restrict__ rb,
                              float* __restrict__ rwOut) {
    size_t t = blockIdx.x;
    const float* x = x2 + t * HID_;
    float s0 = 0, s1 = 0, s2 = 0, s3 = 0;
    for (int j = threadIdx.x; j < HID_; j += 256) {
        float xv = x[j];
        float4 w = ((const float4*)rwW)[j];
        s0 = fmaf(xv, w.x, s0); s1 = fmaf(xv, w.y, s1);
        s2 = fmaf(xv, w.z, s2); s3 = fmaf(xv, w.w, s3);
    }
    __shared__ float sm[8][4];
    int lane = threadIdx.x & 31, w = threadIdx.x >> 5;
    #pragma unroll
    for (int o = 16; o; o >>= 1) {
        s0 += __shfl_down_sync(0xffffffffu, s0, o);
        s1 += __shfl_down_sync(0xffffffffu, s1, o);
        s2 += __shfl_down_sync(0xffffffffu, s2, o);
        s3 += __shfl_down_sync(0xffffffffu, s3, o);
    }
    if (lane == 0) { sm[w][0] = s0; sm[w][1] = s1; sm[w][2] = s2; sm[w][3] = s3; }
    __syncthreads();
    if (threadIdx.x == 0) {
        float l[4];
        #pragma unroll
        for (int e = 0; e < 4; e++) {
            float v = 0;
            #pragma unroll
            for (int ww = 0; ww < 8; ww++) v += sm[ww][e];
            l[e] = v + rb[e];
        }
        float mx = fmaxf(fmaxf(l[0], l[1]), fmaxf(l[2], l[3]));
        float sum = 0;
        #pragma unroll
        for (int e = 0; e < 4; e++) { l[e] = expf(l[e] - mx); sum += l[e]; }
        float inv = 1.f / sum;
        #pragma unroll
        for (int e = 0; e < 4; e++) rwOut[t * E_ + e] = l[e] * inv;
    }
}

// ---------------- balance loss ----------------
__global__ void balance1_kernel(const float* __restrict__ rw, float* __restrict__ red) {
    int s = blockIdx.x;
    if (threadIdx.x < 4) {
        int e = threadIdx.x;
        float m = 0;
        #pragma unroll
        for (int b = 0; b < B_; b++) m += rw[((size_t)(b * S_ + s)) * E_ + e];
        m = m * (1.f / B_) - (1.f / E_);
        float v = m * m;
        v += __shfl_xor_sync(0xF, v, 1);
        v += __shfl_xor_sync(0xF, v, 2);
        if (e == 0) red[s] = v;
    }
}

__global__ void balance2_kernel(const float* __restrict__ red, float* __restrict__ out) {
    float v = red[threadIdx.x] + red[threadIdx.x + 1024];
    v = blk_sum(v);
    if (threadIdx.x == 0) out[0] = v / ((float)S_ * E_) * 0.01f;
}

// ---------------- driver ----------------
extern "C" void kernel_launch(void* const* d_in, const int* in_sizes, int n_in,
                              void* d_out, int out_size) {
    (void)in_sizes; (void)n_in;
    const float* hidden   = (const float*)d_in[0];
    const float* ln1_w    = (const float*)d_in[1];
    const float* wq       = (const float*)d_in[2];
    const float* wk       = (const float*)d_in[3];
    const float* wv       = (const float*)d_in[4];
    const float* wo       = (const float*)d_in[5];
    const float* ln2_w    = (const float*)d_in[6];
    const float* router_w = (const float*)d_in[7];
    const float* router_b = (const float*)d_in[8];
    const float* gate_w   = (const float*)d_in[9];
    const float* up_w     = (const float*)d_in[10];
    const float* down_w   = (const float*)d_in[11];
    float* out = (float*)d_out;

    float *xn, *q, *k, *v, *sc, *o, *h1, *x2, *rw, *gb, *ub, *red;
    cudaGetSymbolAddress((void**)&xn,  g_xn);
    cudaGetSymbolAddress((void**)&q,   g_q);
    cudaGetSymbolAddress((void**)&k,   g_k);
    cudaGetSymbolAddress((void**)&v,   g_v);
    cudaGetSymbolAddress((void**)&sc,  g_scores);
    cudaGetSymbolAddress((void**)&o,   g_o);
    cudaGetSymbolAddress((void**)&h1,  g_h1);
    cudaGetSymbolAddress((void**)&x2,  g_x2);
    cudaGetSymbolAddress((void**)&rw,  g_rw);
    cudaGetSymbolAddress((void**)&gb,  g_gbuf);
    cudaGetSymbolAddress((void**)&ub,  g_ubuf);
    cudaGetSymbolAddress((void**)&red, g_red);

    // 1) rmsnorm 1
    rmsnorm_kernel<<<T_, 256>>>(hidden, ln1_w, xn);

    // 2) Q,K,V projections (elu+1 fused into Q,K)
    dim3 gproj(HID_ / BN, T_ / BM, 1);
    gemm_kernel<1, false><<<gproj, 256>>>(T_, HID_, HID_, xn, HID_, 0, 0,
                                          wq, HID_, 0, 0, q, HID_, 0, 0,
                                          nullptr, nullptr, 0);
    gemm_kernel<1, false><<<gproj, 256>>>(T_, HID_, HID_, xn, HID_, 0, 0,
                                          wk, HID_, 0, 0, k, HID_, 0, 0,
                                          nullptr, nullptr, 0);
    gemm_kernel<0, false><<<gproj, 256>>>(T_, HID_, HID_, xn, HID_, 0, 0,
                                          wv, HID_, 0, 0, v, HID_, 0, 0,
                                          nullptr, nullptr, 0);

    // 3) scores = Q @ K^T, batched over (b,h)
    dim3 gsc(S_ / BN, S_ / BM, B_ * NH_);
    gemm_kernel<0, true><<<gsc, 256>>>(S_, S_, D_,
                                       q, HID_, (long)S_ * HID_, D_,
                                       k, HID_, (long)S_ * HID_, D_,
                                       sc, S_, (long)NH_ * S_ * S_, (long)S_ * S_,
                                       nullptr, nullptr, 0);

    // 4) row softmax
    softmax_kernel<<<B_ * NH_ * S_, 256>>>(sc);

    // 5) O = attn @ V, batched
    dim3 gpv(D_ / BN, S_ / BM, B_ * NH_);
    gemm_kernel<0, false><<<gpv, 256>>>(S_, D_, S_,
                                        sc, S_, (long)NH_ * S_ * S_, (long)S_ * S_,
                                        v, HID_, (long)S_ * HID_, D_,
                                        o, HID_, (long)S_ * HID_, D_,
                                        nullptr, nullptr, 0);

    // 6) h1 = hidden + O @ Wo
    gemm_kernel<2, false><<<gproj, 256>>>(T_, HID_, HID_, o, HID_, 0, 0,
                                          wo, HID_, 0, 0, h1, HID_, 0, 0,
                                          hidden, nullptr, 0);

    // 7) rmsnorm 2
    rmsnorm_kernel<<<T_, 256>>>(h1, ln2_w, x2);

    // 8) router softmax
    router_kernel<<<T_, 256>>>(x2, router_w, router_b, rw);

    // 9) balance loss -> d_out[T_*HID_]
    if (out_size > T_ * HID_) {
        balance1_kernel<<<S_, 32>>>(rw, red);
        balance2_kernel<<<1, 1024>>>(red, out + (size_t)T_ * HID_);
    }

    // 10) MoE: dense expert loop; out seeded with h1 via expert-0 epilogue
    dim3 gmoe(IM_ / BN, T_ / BM, 1);
    dim3 gdown(HID_ / BN, T_ / BM, 1);
    for (int i = 0; i < E_; i++) {
        const float* gw = gate_w + (long)i * HID_ * IM_;
        const float* uw = up_w   + (long)i * HID_ * IM_;
        const float* dw = down_w + (long)i * IM_ * HID_;
        gemm_kernel<3, false><<<gmoe, 256>>>(T_, IM_, HID_, x2, HID_, 0, 0,
                                             gw, IM_, 0, 0, gb, IM_, 0, 0,
                                             nullptr, nullptr, 0);
        gemm_kernel<4, false><<<gmoe, 256>>>(T_, IM_, HID_, x2, HID_, 0, 0,
                                             uw, IM_, 0, 0, ub, IM_, 0, 0,
                                             gb, nullptr, 0);
        if (i == 0)
            gemm_kernel<5, false><<<gdown, 256>>>(T_, HID_, IM_, ub, IM_, 0, 0,
                                                  dw, HID_, 0, 0, out, HID_, 0, 0,
                                                  h1, rw + i, E_);
        else
            gemm_kernel<6, false><<<gdown, 256>>>(T_, HID_, IM_, ub, IM_, 0, 0,
                                                  dw, HID_, 0, 0, out, HID_, 0, 0,
                                                  nullptr, rw + i, E_);
    }
}

// round 2
// speedup vs baseline: 2.1217x; 2.1217x over previous
#include <cuda_runtime.h>
#include <math.h>

#define B_   4
#define S_   2048
#define HID_ 1024
#define NH_  4
#define D_   256
#define IM_  2048
#define E_   4
#define T_   (B_*S_)   // 8192 tokens

// ---------------- scratch (static device allocations; allowed) ----------------
__device__ float g_xn[(size_t)T_*HID_];
__device__ float g_q [(size_t)T_*HID_];
__device__ float g_k [(size_t)T_*HID_];
__device__ float g_v [(size_t)T_*HID_];
__device__ float g_scores[(size_t)B_*NH_*S_*S_];   // 256 MB
__device__ float g_o [(size_t)T_*HID_];
__device__ float g_h1[(size_t)T_*HID_];
__device__ float g_x2[(size_t)T_*HID_];
__device__ float g_rw[(size_t)T_*E_];
__device__ float g_gbuf[(size_t)T_*IM_];
__device__ float g_ubuf[(size_t)T_*IM_];
__device__ float g_red[S_];

// ---------------- block reductions ----------------
__device__ __forceinline__ float blk_sum(float v) {
    __shared__ float sm[32];
    __syncthreads();
    int lane = threadIdx.x & 31, w = threadIdx.x >> 5;
    #pragma unroll
    for (int o = 16; o; o >>= 1) v += __shfl_down_sync(0xffffffffu, v, o);
    if (lane == 0) sm[w] = v;
    __syncthreads();
    int nw = blockDim.x >> 5;
    if (w == 0) {
        v = (lane < nw) ? sm[lane] : 0.f;
        #pragma unroll
        for (int o = 16; o; o >>= 1) v += __shfl_down_sync(0xffffffffu, v, o);
        if (lane == 0) sm[0] = v;
    }
    __syncthreads();
    return sm[0];
}

__device__ __forceinline__ float blk_max(float v) {
    __shared__ float sm[32];
    __syncthreads();
    int lane = threadIdx.x & 31, w = threadIdx.x >> 5;
    #pragma unroll
    for (int o = 16; o; o >>= 1) v = fmaxf(v, __shfl_down_sync(0xffffffffu, v, o));
    if (lane == 0) sm[w] = v;
    __syncthreads();
    int nw = blockDim.x >> 5;
    if (w == 0) {
        v = (lane < nw) ? sm[lane] : -INFINITY;
        #pragma unroll
        for (int o = 16; o; o >>= 1) v = fmaxf(v, __shfl_down_sync(0xffffffffu, v, o));
        if (lane == 0) sm[0] = v;
    }
    __syncthreads();
    return sm[0];
}

// ---------------- rmsnorm ----------------
__global__ void rmsnorm_kernel(const float* __restrict__ x,
                               const float* __restrict__ w,
                               float* __restrict__ out) {
    size_t t = blockIdx.x;
    const float4* xp = (const float4*)(x + t * HID_);
    float4 v = xp[threadIdx.x];
    float s = v.x*v.x + v.y*v.y + v.z*v.z + v.w*v.w;
    s = blk_sum(s);
    float r = rsqrtf(s * (1.f / HID_) + 1e-6f);
    float4 wv = ((const float4*)w)[threadIdx.x];
    float4 o;
    o.x = v.x * wv.x * r; o.y = v.y * wv.y * r;
    o.z = v.z * wv.z * r; o.w = v.w * wv.w * r;
    ((float4*)(out + t * HID_))[threadIdx.x] = o;
}

// ================= legacy fp32 SGEMM (kept for the precision-critical QK chain) =================
#define BM 128
#define BN 128
#define BK 16
#define TM 8
#define TN 8

template<int EPI, bool TB>
__global__ __launch_bounds__(256)
void gemm_kernel(int M, int N, int K,
                 const float* __restrict__ A, int lda, long sAb, long sAh,
                 const float* __restrict__ Bm, int ldb, long sBb, long sBh,
                 float* __restrict__ C, int ldc, long sCb, long sCh,
                 const float* __restrict__ aux,
                 const float* __restrict__ rs, int rsStride) {
    int z  = blockIdx.z;
    int zb = z >> 2, zh = z & 3;
    A  += (long)zb * sAb + (long)zh * sAh;
    Bm += (long)zb * sBb + (long)zh * sBh;
    C  += (long)zb * sCb + (long)zh * sCh;

    __shared__ float As[BK][BM];
    __shared__ float Bs[BK][BN];

    int tid = threadIdx.x;
    int blockRow = blockIdx.y * BM;
    int blockCol = blockIdx.x * BN;
    int trow = (tid >> 4) * TM;
    int tcol = (tid & 15) * TN;

    int aRow = tid >> 2;
    int aCol = (tid & 3) * 4;
    int bRow = tid >> 5;
    int bCol = (tid & 31) * 4;

    float acc[TM][TN] = {};

    for (int k0 = 0; k0 < K; k0 += BK) {
        #pragma unroll
        for (int p = 0; p < 2; p++) {
            int r = aRow + p * 64;
            float4 v = *(const float4*)(A + (long)(blockRow + r) * lda + k0 + aCol);
            As[aCol + 0][r] = v.x; As[aCol + 1][r] = v.y;
            As[aCol + 2][r] = v.z; As[aCol + 3][r] = v.w;
        }
        if (!TB) {
            #pragma unroll
            for (int p = 0; p < 2; p++) {
                int r = bRow + p * 8;
                *(float4*)(&Bs[r][bCol]) =
                    *(const float4*)(Bm + (long)(k0 + r) * ldb + blockCol + bCol);
            }
        } else {
            #pragma unroll
            for (int p = 0; p < 2; p++) {
                int n = aRow + p * 64;
                float4 v = *(const float4*)(Bm + (long)(blockCol + n) * ldb + k0 + aCol);
                Bs[aCol + 0][n] = v.x; Bs[aCol + 1][n] = v.y;
                Bs[aCol + 2][n] = v.z; Bs[aCol + 3][n] = v.w;
            }
        }
        __syncthreads();

        #pragma unroll
        for (int kk = 0; kk < BK; kk++) {
            float ar[TM], br[TN];
            #pragma unroll
            for (int i = 0; i < TM; i++) ar[i] = As[kk][trow + i];
            #pragma unroll
            for (int j = 0; j < TN; j++) br[j] = Bs[kk][tcol + j];
            #pragma unroll
            for (int i = 0; i < TM; i++)
                #pragma unroll
                for (int j = 0; j < TN; j++)
                    acc[i][j] = fmaf(ar[i], br[j], acc[i][j]);
        }
        __syncthreads();
    }

    #pragma unroll
    for (int i = 0; i < TM; i++) {
        int m = blockRow + trow + i;
        #pragma unroll
        for (int j = 0; j < TN; j++) {
            int n = blockCol + tcol + j;
            long idx = (long)m * ldc + n;
            float v = acc[i][j];
            if      (EPI == 0) C[idx] = v;
            else if (EPI == 1) C[idx] = (v > 0.f) ? v + 1.f : expf(v);     // elu+1
            else if (EPI == 2) C[idx] = v + aux[idx];
        }
    }
}

// ================= tf32 tensor-core GEMM =================
// C[M,N] = A[M,K] * B[K,N], all row-major, batched over blockIdx.z ((b,h) split).
// EPI: 0 store, 2 +aux, 3 silu, 4 *aux, 5 aux + acc*rs[m], 6 C += acc*rs[m]
#define TBM 128
#define TBN 128
#define TBK 16
#define ASTR 136
#define BSTR 136

__device__ __forceinline__ unsigned f2tf(float x) {
    unsigned r;
    asm("cvt.rna.tf32.f32 %0, %1;" : "=r"(r) : "f"(x));
    return r;
}

__device__ __forceinline__ void mma_tf32(float* c, const unsigned* a, const unsigned* b) {
    asm volatile("mma.sync.aligned.m16n8k8.row.col.f32.tf32.tf32.f32 "
                 "{%0,%1,%2,%3},{%4,%5,%6,%7},{%8,%9},{%0,%1,%2,%3};"
                 : "+f"(c[0]), "+f"(c[1]), "+f"(c[2]), "+f"(c[3])
                 : "r"(a[0]), "r"(a[1]), "r"(a[2]), "r"(a[3]),
                   "r"(b[0]), "r"(b[1]));
}

template<int EPI>
__global__ __launch_bounds__(256, 2)
void tgemm(int M, int N, int K,
           const float* __restrict__ A, int lda, long sAb, long sAh,
           const float* __restrict__ Bm, int ldb, long sBb, long sBh,
           float* __restrict__ C, int ldc, long sCb, long sCh,
           const float* __restrict__ aux,
           const float* __restrict__ rs, int rsStride) {
    int z  = blockIdx.z;
    int zb = z >> 2, zh = z & 3;
    A  += (long)zb * sAb + (long)zh * sAh;
    Bm += (long)zb * sBb + (long)zh * sBh;
    C  += (long)zb * sCb + (long)zh * sCh;

    __shared__ float As[TBK][ASTR];   // [k][m], tf32 bits
    __shared__ float Bs[TBK][BSTR];   // [k][n], tf32 bits

    int tid  = threadIdx.x;
    int lane = tid & 31;
    int warp = tid >> 5;
    int wm = (warp >> 2) * 64;        // warp row base within tile
    int wn = (warp & 3) * 32;         // warp col base within tile
    int g = lane >> 2;                // 0..7
    int t = lane & 3;                 // 0..3

    int blockRow = blockIdx.y * TBM;
    int blockCol = blockIdx.x * TBN;

    // loader mappings
    int aRow = tid >> 2;              // 0..63 (+64 for p=1)
    int aCol = (tid & 3) * 4;         // k offset
    int bRow = tid >> 5;              // 0..7  (+8 for p=1)
    int bCol = (tid & 31) * 4;        // n offset

    float acc[4][4][4] = {};          // [mi][ni][frag]
    float4 pa[2], pb[2];

    int nIter = K / TBK;
    const float* Aptr = A + (long)blockRow * lda + aCol;
    const float* Bptr = Bm + blockCol + bCol;

    // prologue: load tile 0
    {
        #pragma unroll
        for (int p = 0; p < 2; p++)
            pa[p] = *(const float4*)(Aptr + (long)(aRow + p * 64) * lda);
        #pragma unroll
        for (int p = 0; p < 2; p++)
            pb[p] = *(const float4*)(Bptr + (long)(bRow + p * 8) * ldb);
    }

    for (int it = 0; it < nIter; it++) {
        // store prefetched tile to smem (fp32 -> tf32)
        #pragma unroll
        for (int p = 0; p < 2; p++) {
            int r = aRow + p * 64;
            As[aCol + 0][r] = __uint_as_float(f2tf(pa[p].x));
            As[aCol + 1][r] = __uint_as_float(f2tf(pa[p].y));
            As[aCol + 2][r] = __uint_as_float(f2tf(pa[p].z));
            As[aCol + 3][r] = __uint_as_float(f2tf(pa[p].w));
        }
        #pragma unroll
        for (int p = 0; p < 2; p++) {
            int r = bRow + p * 8;
            float4 cv;
            cv.x = __uint_as_float(f2tf(pb[p].x));
            cv.y = __uint_as_float(f2tf(pb[p].y));
            cv.z = __uint_as_float(f2tf(pb[p].z));
            cv.w = __uint_as_float(f2tf(pb[p].w));
            *(float4*)(&Bs[r][bCol]) = cv;
        }
        __syncthreads();

        // prefetch next tile
        if (it + 1 < nIter) {
            long ko = (long)(it + 1) * TBK;
            #pragma unroll
            for (int p = 0; p < 2; p++)
                pa[p] = *(const float4*)(Aptr + (long)(aRow + p * 64) * lda + ko);
            #pragma unroll
            for (int p = 0; p < 2; p++)
                pb[p] = *(const float4*)(Bptr + (long)(bRow + p * 8 + ko) * ldb);
        }

        // compute 2 k8-steps
        #pragma unroll
        for (int kb = 0; kb < TBK; kb += 8) {
            unsigned a[4][4], b[4][2];
            #pragma unroll
            for (int mi = 0; mi < 4; mi++) {
                int m0 = wm + mi * 16 + g;
                a[mi][0] = __float_as_uint(As[kb + t][m0]);
                a[mi][1] = __float_as_uint(As[kb + t][m0 + 8]);
                a[mi][2] = __float_as_uint(As[kb + t + 4][m0]);
                a[mi][3] = __float_as_uint(As[kb + t + 4][m0 + 8]);
            }
            #pragma unroll
            for (int ni = 0; ni < 4; ni++) {
                int n0 = wn + ni * 8 + g;
                b[ni][0] = __float_as_uint(Bs[kb + t][n0]);
                b[ni][1] = __float_as_uint(Bs[kb + t + 4][n0]);
            }
            #pragma unroll
            for (int mi = 0; mi < 4; mi++)
                #pragma unroll
                for (int ni = 0; ni < 4; ni++)
                    mma_tf32(acc[mi][ni], a[mi], b[ni]);
        }
        __syncthreads();
    }

    // epilogue
    #pragma unroll
    for (int mi = 0; mi < 4; mi++) {
        int r0 = blockRow + wm + mi * 16 + g;
        int r1 = r0 + 8;
        float sc0 = 0.f, sc1 = 0.f;
        if (EPI == 5 || EPI == 6) {
            sc0 = rs[(long)r0 * rsStride];
            sc1 = rs[(long)r1 * rsStride];
        }
        #pragma unroll
        for (int ni = 0; ni < 4; ni++) {
            int col = blockCol + wn + ni * 8 + 2 * t;
            long i0 = (long)r0 * ldc + col;
            long i1 = (long)r1 * ldc + col;
            float v0 = acc[mi][ni][0], v1 = acc[mi][ni][1];
            float v2 = acc[mi][ni][2], v3 = acc[mi][ni][3];
            float2 o0, o1;
            if (EPI == 0) {
                o0 = make_float2(v0, v1);
                o1 = make_float2(v2, v3);
            } else if (EPI == 2) {
                float2 x0 = *(const float2*)(aux + i0);
                float2 x1 = *(const float2*)(aux + i1);
                o0 = make_float2(v0 + x0.x, v1 + x0.y);
                o1 = make_float2(v2 + x1.x, v3 + x1.y);
            } else if (EPI == 3) {
                o0 = make_float2(v0 / (1.f + expf(-v0)), v1 / (1.f + expf(-v1)));
                o1 = make_float2(v2 / (1.f + expf(-v2)), v3 / (1.f + expf(-v3)));
            } else if (EPI == 4) {
                float2 x0 = *(const float2*)(aux + i0);
                float2 x1 = *(const float2*)(aux + i1);
                o0 = make_float2(v0 * x0.x, v1 * x0.y);
                o1 = make_float2(v2 * x1.x, v3 * x1.y);
            } else if (EPI == 5) {
                float2 x0 = *(const float2*)(aux + i0);
                float2 x1 = *(const float2*)(aux + i1);
                o0 = make_float2(x0.x + v0 * sc0, x0.y + v1 * sc0);
                o1 = make_float2(x1.x + v2 * sc1, x1.y + v3 * sc1);
            } else { // EPI == 6
                float2 x0 = *(const float2*)(C + i0);
                float2 x1 = *(const float2*)(C + i1);
                o0 = make_float2(x0.x + v0 * sc0, x0.y + v1 * sc0);
                o1 = make_float2(x1.x + v2 * sc1, x1.y + v3 * sc1);
            }
            *(float2*)(C + i0) = o0;
            *(float2*)(C + i1) = o1;
        }
    }
}

// ---------------- softmax over rows of length S_=2048 ----------------
__global__ void softmax_kernel(float* __restrict__ x) {
    size_t row = blockIdx.x;
    float4* p = (float4*)(x + row * (size_t)S_);
    float4 a = p[threadIdx.x];
    float4 b = p[threadIdx.x + 256];
    float mx = fmaxf(fmaxf(fmaxf(a.x, a.y), fmaxf(a.z, a.w)),
                     fmaxf(fmaxf(b.x, b.y), fmaxf(b.z, b.w)));
    mx = blk_max(mx);
    a.x = expf(a.x - mx); a.y = expf(a.y - mx); a.z = expf(a.z - mx); a.w = expf(a.w - mx);
    b.x = expf(b.x - mx); b.y = expf(b.y - mx); b.z = expf(b.z - mx); b.w = expf(b.w - mx);
    float s = a.x + a.y + a.z + a.w + b.x + b.y + b.z + b.w;
    s = blk_sum(s);
    float inv = 1.f / s;
    a.x *= inv; a.y *= inv; a.z *= inv; a.w *= inv;
    b.x *= inv; b.y *= inv; b.z *= inv; b.w *= inv;
    p[threadIdx.x] = a;
    p[threadIdx.x + 256] = b;
}

// ---------------- router ----------------
__global__ void router_kernel(const float* __restrict__ x2,
                              const float* __restrict__ rwW,
                              const float* __restrict__ rb,
                              float* __restrict__ rwOut) {
    size_t t = blockIdx.x;
    const float* x = x2 + t * HID_;
    float s0 = 0, s1 = 0, s2 = 0, s3 = 0;
    for (int j = threadIdx.x; j < HID_; j += 256) {
        float xv = x[j];
        float4 w = ((const float4*)rwW)[j];
        s0 = fmaf(xv, w.x, s0); s1 = fmaf(xv, w.y, s1);
        s2 = fmaf(xv, w.z, s2); s3 = fmaf(xv, w.w, s3);
    }
    __shared__ float sm[8][4];
    int lane = threadIdx.x & 31, w = threadIdx.x >> 5;
    #pragma unroll
    for (int o = 16; o; o >>= 1) {
        s0 += __shfl_down_sync(0xffffffffu, s0, o);
        s1 += __shfl_down_sync(0xffffffffu, s1, o);
        s2 += __shfl_down_sync(0xffffffffu, s2, o);
        s3 += __shfl_down_sync(0xffffffffu, s3, o);
    }
    if (lane == 0) { sm[w][0] = s0; sm[w][1] = s1; sm[w][2] = s2; sm[w][3] = s3; }
    __syncthreads();
    if (threadIdx.x == 0) {
        float l[4];
        #pragma unroll
        for (int e = 0; e < 4; e++) {
            float v = 0;
            #pragma unroll
            for (int ww = 0; ww < 8; ww++) v += sm[ww][e];
            l[e] = v + rb[e];
        }
        float mx = fmaxf(fmaxf(l[0], l[1]), fmaxf(l[2], l[3]));
        float sum = 0;
        #pragma unroll
        for (int e = 0; e < 4; e++) { l[e] = expf(l[e] - mx); sum += l[e]; }
        float inv = 1.f / sum;
        #pragma unroll
        for (int e = 0; e < 4; e++) rwOut[t * E_ + e] = l[e] * inv;
    }
}

// ---------------- balance loss ----------------
__global__ void balance1_kernel(const float* __restrict__ rw, float* __restrict__ red) {
    int s = blockIdx.x;
    if (threadIdx.x < 4) {
        int e = threadIdx.x;
        float m = 0;
        #pragma unroll
        for (int b = 0; b < B_; b++) m += rw[((size_t)(b * S_ + s)) * E_ + e];
        m = m * (1.f / B_) - (1.f / E_);
        float v = m * m;
        v += __shfl_xor_sync(0xF, v, 1);
        v += __shfl_xor_sync(0xF, v, 2);
        if (e == 0) red[s] = v;
    }
}

__global__ void balance2_kernel(const float* __restrict__ red, float* __restrict__ out) {
    float v = red[threadIdx.x] + red[threadIdx.x + 1024];
    v = blk_sum(v);
    if (threadIdx.x == 0) out[0] = v / ((float)S_ * E_) * 0.01f;
}

// ---------------- driver ----------------
extern "C" void kernel_launch(void* const* d_in, const int* in_sizes, int n_in,
                              void* d_out, int out_size) {
    (void)in_sizes; (void)n_in;
    const float* hidden   = (const float*)d_in[0];
    const float* ln1_w    = (const float*)d_in[1];
    const float* wq       = (const float*)d_in[2];
    const float* wk       = (const float*)d_in[3];
    const float* wv       = (const float*)d_in[4];
    const float* wo       = (const float*)d_in[5];
    const float* ln2_w    = (const float*)d_in[6];
    const float* router_w = (const float*)d_in[7];
    const float* router_b = (const float*)d_in[8];
    const float* gate_w   = (const float*)d_in[9];
    const float* up_w     = (const float*)d_in[10];
    const float* down_w   = (const float*)d_in[11];
    float* out = (float*)d_out;

    float *xn, *q, *k, *v, *sc, *o, *h1, *x2, *rw, *gb, *ub, *red;
    cudaGetSymbolAddress((void**)&xn,  g_xn);
    cudaGetSymbolAddress((void**)&q,   g_q);
    cudaGetSymbolAddress((void**)&k,   g_k);
    cudaGetSymbolAddress((void**)&v,   g_v);
    cudaGetSymbolAddress((void**)&sc,  g_scores);
    cudaGetSymbolAddress((void**)&o,   g_o);
    cudaGetSymbolAddress((void**)&h1,  g_h1);
    cudaGetSymbolAddress((void**)&x2,  g_x2);
    cudaGetSymbolAddress((void**)&rw,  g_rw);
    cudaGetSymbolAddress((void**)&gb,  g_gbuf);
    cudaGetSymbolAddress((void**)&ub,  g_ubuf);
    cudaGetSymbolAddress((void**)&red, g_red);

    // 1) rmsnorm 1
    rmsnorm_kernel<<<T_, 256>>>(hidden, ln1_w, xn);

    dim3 gproj(HID_ / TBN, T_ / TBM, 1);

    // 2) Q,K projections in fp32 (precision-critical for softmax), V in tf32
    gemm_kernel<1, false><<<gproj, 256>>>(T_, HID_, HID_, xn, HID_, 0, 0,
                                          wq, HID_, 0, 0, q, HID_, 0, 0,
                                          nullptr, nullptr, 0);
    gemm_kernel<1, false><<<gproj, 256>>>(T_, HID_, HID_, xn, HID_, 0, 0,
                                          wk, HID_, 0, 0, k, HID_, 0, 0,
                                          nullptr, nullptr, 0);
    tgemm<0><<<gproj, 256>>>(T_, HID_, HID_, xn, HID_, 0, 0,
                             wv, HID_, 0, 0, v, HID_, 0, 0,
                             nullptr, nullptr, 0);

    // 3) scores = Q @ K^T in fp32 (precision-critical), batched over (b,h)
    dim3 gsc(S_ / BN, S_ / BM, B_ * NH_);
    gemm_kernel<0, true><<<gsc, 256>>>(S_, S_, D_,
                                       q, HID_, (long)S_ * HID_, D_,
                                       k, HID_, (long)S_ * HID_, D_,
                                       sc, S_, (long)NH_ * S_ * S_, (long)S_ * S_,
                                       nullptr, nullptr, 0);

    // 4) row softmax
    softmax_kernel<<<B_ * NH_ * S_, 256>>>(sc);

    // 5) O = attn @ V (tf32), batched
    dim3 gpv(D_ / TBN, S_ / TBM, B_ * NH_);
    tgemm<0><<<gpv, 256>>>(S_, D_, S_,
                           sc, S_, (long)NH_ * S_ * S_, (long)S_ * S_,
                           v, HID_, (long)S_ * HID_, D_,
                           o, HID_, (long)S_ * HID_, D_,
                           nullptr, nullptr, 0);

    // 6) h1 = hidden + O @ Wo (tf32)
    tgemm<2><<<gproj, 256>>>(T_, HID_, HID_, o, HID_, 0, 0,
                             wo, HID_, 0, 0, h1, HID_, 0, 0,
                             hidden, nullptr, 0);

    // 7) rmsnorm 2
    rmsnorm_kernel<<<T_, 256>>>(h1, ln2_w, x2);

    // 8) router softmax
    router_kernel<<<T_, 256>>>(x2, router_w, router_b, rw);

    // 9) balance loss -> d_out[T_*HID_]
    if (out_size > T_ * HID_) {
        balance1_kernel<<<S_, 32>>>(rw, red);
        balance2_kernel<<<1, 1024>>>(red, out + (size_t)T_ * HID_);
    }

    // 10) MoE (all tf32): dense expert loop; out seeded with h1 via expert-0 epilogue
    dim3 gmoe(IM_ / TBN, T_ / TBM, 1);
    dim3 gdown(HID_ / TBN, T_ / TBM, 1);
    for (int i = 0; i < E_; i++) {
        const float* gw = gate_w + (long)i * HID_ * IM_;
        const float* uw = up_w   + (long)i * HID_ * IM_;
        const float* dw = down_w + (long)i * IM_ * HID_;
        tgemm<3><<<gmoe, 256>>>(T_, IM_, HID_, x2, HID_, 0, 0,
                                gw, IM_, 0, 0, gb, IM_, 0, 0,
                                nullptr, nullptr, 0);
        tgemm<4><<<gmoe, 256>>>(T_, IM_, HID_, x2, HID_, 0, 0,
                                uw, IM_, 0, 0, ub, IM_, 0, 0,
                                gb, nullptr, 0);
        if (i == 0)
            tgemm<5><<<gdown, 256>>>(T_, HID_, IM_, ub, IM_, 0, 0,
                                     dw, HID_, 0, 0, out, HID_, 0, 0,
                                     h1, rw + i, E_);
        else
            tgemm<6><<<gdown, 256>>>(T_, HID_, IM_, ub, IM_, 0, 0,
                                     dw, HID_, 0, 0, out, HID_, 0, 0,
                                     nullptr, rw + i, E_);
    }
}